// round 7
// baseline (speedup 1.0000x reference)
#include <cuda_runtime.h>
#include <cuda_fp16.h>
#include <cstdint>

#define KC   512
#define DD   64
#define TPB  256
#define BN   128
#define NCH  8       // 8 chunks of 64 codes
#define LDA  72      // fp16 elems per row (144B)
#define ROWB 144

#define OFF_AH   0
#define OFF_AM   18432
#define OFF_BB   36864                 // 2 bufs x (H 9216 + M 9216)
#define BUFSZ    18432
#define OFF_HWW  73728                 // 2 x 64 f32
#define OFF_SBV  (OFF_HWW + 512)
#define OFF_SBI  (OFF_SBV + 1024)
#define OFF_KIDX (OFF_SBI + 1024)
#define OFF_SRED (OFF_KIDX + 512)
#define SMEM_TOTAL (OFF_SRED + 64)

__device__ __align__(16) __half g_bh[KC * LDA];
__device__ __align__(16) __half g_bm[KC * LDA];
__device__ __align__(16) float  g_hww[KC];
__device__ double   g_loss_sum;
__device__ unsigned g_ctr;

#define LDSM4(r0, r1, r2, r3, addr) \
    asm volatile("ldmatrix.sync.aligned.m8n8.x4.shared.b16 {%0,%1,%2,%3}, [%4];" \
                 : "=r"(r0), "=r"(r1), "=r"(r2), "=r"(r3) : "r"(addr))

#define MMA(d, a, b) \
    asm volatile("mma.sync.aligned.m16n8k16.row.col.f32.f16.f16.f32 " \
                 "{%0,%1,%2,%3}, {%4,%5,%6,%7}, {%8,%9}, {%0,%1,%2,%3};" \
                 : "+f"((d)[0]), "+f"((d)[1]), "+f"((d)[2]), "+f"((d)[3]) \
                 : "r"((a)[0]), "r"((a)[1]), "r"((a)[2]), "r"((a)[3]), \
                   "r"((b)[0]), "r"((b)[1]))

#define CPA16(dst, src) \
    asm volatile("cp.async.cg.shared.global [%0], [%1], 16;" :: "r"(dst), "l"(src))

// ---- pre-split: emb [64][512] fp32 -> g_bh/g_bm [512][72] fp16 + g_hww ----
__global__ void __launch_bounds__(128)
vq_pre_kernel(const float* __restrict__ emb)
{
    __shared__ float sp[4][32];
    const int t = threadIdx.x;
    const int c = blockIdx.x * 32 + (t & 31);
    const int dseg = (t >> 5) * 16;

    uint32_t hw[8], mw[8];
    float s = 0.f;
    #pragma unroll
    for (int j = 0; j < 8; j++) {
        float e0 = __ldg(emb + (size_t)(dseg + 2 * j) * KC + c);
        float e1 = __ldg(emb + (size_t)(dseg + 2 * j + 1) * KC + c);
        s = fmaf(e1, e1, fmaf(e0, e0, s));
        __half h0 = __float2half_rn(e0), h1 = __float2half_rn(e1);
        __half m0 = __float2half_rn(e0 - __half2float(h0));
        __half m1 = __float2half_rn(e1 - __half2float(h1));
        hw[j] = (uint32_t)__half_as_ushort(h0) | ((uint32_t)__half_as_ushort(h1) << 16);
        mw[j] = (uint32_t)__half_as_ushort(m0) | ((uint32_t)__half_as_ushort(m1) << 16);
    }
    *(uint4*)(g_bh + c * LDA + dseg)     = make_uint4(hw[0], hw[1], hw[2], hw[3]);
    *(uint4*)(g_bh + c * LDA + dseg + 8) = make_uint4(hw[4], hw[5], hw[6], hw[7]);
    *(uint4*)(g_bm + c * LDA + dseg)     = make_uint4(mw[0], mw[1], mw[2], mw[3]);
    *(uint4*)(g_bm + c * LDA + dseg + 8) = make_uint4(mw[4], mw[5], mw[6], mw[7]);
    sp[t >> 5][t & 31] = s;
    __syncthreads();
    if (t < 32)
        g_hww[blockIdx.x * 32 + t] = 0.5f * (sp[0][t] + sp[1][t] + sp[2][t] + sp[3][t]);
}

// issue async copy of one 64-code chunk into buffer buf
__device__ __forceinline__ void issue_chunk(uint32_t sb, int chunk, int buf, int t)
{
    const char* srcH = (const char*)g_bh + (size_t)chunk * 64 * ROWB;
    const char* srcM = (const char*)g_bm + (size_t)chunk * 64 * ROWB;
    const uint32_t dstH = sb + OFF_BB + buf * BUFSZ;
    const uint32_t dstM = dstH + 9216;
    #pragma unroll
    for (int i = t; i < 576; i += TPB) {       // 64*144B/16
        CPA16(dstH + i * 16, srcH + i * 16);
        CPA16(dstM + i * 16, srcM + i * 16);
    }
    if (t < 16) CPA16(sb + OFF_HWW + buf * 256 + t * 16,
                      (const char*)g_hww + chunk * 256 + t * 16);
    asm volatile("cp.async.commit_group;");
}

__global__ void __launch_bounds__(TPB, 2)
vq_main_kernel(const float* __restrict__ x, float* __restrict__ out_q,
               float* __restrict__ out_idx, float* __restrict__ out_loss,
               int n_rows, double inv_count)
{
    extern __shared__ char smem[];
    const uint32_t sb = (uint32_t)__cvta_generic_to_shared(smem);
    const int t = threadIdx.x, lane = t & 31, w = t >> 5;
    const int wm = w >> 1, wn = w & 1;       // 4 m-warps x 2 n-warps
    const int rowbase = blockIdx.x * BN;

    // prefetch chunks 0 and 1 (overlaps the A split below)
    issue_chunk(sb, 0, 0, t);
    issue_chunk(sb, 1, 1, t);

    // ---- A split: x rows -> h (AH) + m (AM) fp16 tiles ----
    {
        const int row = t >> 1, hseg = (t & 1) * 32;
        const bool v = (rowbase + row) < n_rows;
        const float4* xr = (const float4*)(x + (size_t)(rowbase + row) * DD + hseg);
        __half* ah = (__half*)(smem + OFF_AH) + row * LDA + hseg;
        __half* am = (__half*)(smem + OFF_AM) + row * LDA + hseg;
        #pragma unroll
        for (int j = 0; j < 8; j++) {
            float4 f = v ? xr[j] : make_float4(0.f, 0.f, 0.f, 0.f);
            float e[4] = {f.x, f.y, f.z, f.w};
            __half h[4], m[4];
            #pragma unroll
            for (int p = 0; p < 4; p++) {
                h[p] = __float2half_rn(e[p]);
                m[p] = __float2half_rn(e[p] - __half2float(h[p]));
            }
            *(__half2*)(ah + 4 * j)     = __halves2half2(h[0], h[1]);
            *(__half2*)(ah + 4 * j + 2) = __halves2half2(h[2], h[3]);
            *(__half2*)(am + 4 * j)     = __halves2half2(m[0], m[1]);
            *(__half2*)(am + 4 * j + 2) = __halves2half2(m[2], m[3]);
        }
    }
    __syncthreads();   // A tiles ready for ldmatrix

    // ---- hoist A fragments into registers (invariant across all chunks) ----
    const uint32_t a_off = (uint32_t)((wm * 32 + (lane & 15)) * ROWB + (((lane >> 4) << 3) << 1));
    uint32_t ah[2][4][4], am[2][4][4];
    #pragma unroll
    for (int kc = 0; kc < 4; kc++) {
        const uint32_t ka = (uint32_t)(kc * 32);
        LDSM4(ah[0][kc][0], ah[0][kc][1], ah[0][kc][2], ah[0][kc][3], sb + OFF_AH + a_off + ka);
        LDSM4(ah[1][kc][0], ah[1][kc][1], ah[1][kc][2], ah[1][kc][3], sb + OFF_AH + a_off + ka + 16 * ROWB);
        LDSM4(am[0][kc][0], am[0][kc][1], am[0][kc][2], am[0][kc][3], sb + OFF_AM + a_off + ka);
        LDSM4(am[1][kc][0], am[1][kc][1], am[1][kc][2], am[1][kc][3], sb + OFF_AM + a_off + ka + 16 * ROWB);
    }

    float best[4];
    int   bk[4];
    #pragma unroll
    for (int s = 0; s < 4; s++) { best[s] = -3.402823466e38f; bk[s] = 0; }

    const uint32_t b_off = (uint32_t)(((lane & 7) + ((lane >> 4) << 3) + wn * 32) * ROWB
                                      + ((((lane >> 3) & 1) << 3) << 1));

    #pragma unroll 1
    for (int c = 0; c < NCH; c++) {
        const int buf = c & 1;
        const uint32_t bbase = sb + OFF_BB + buf * BUFSZ;

        if (c < NCH - 1) asm volatile("cp.async.wait_group 1;" ::: "memory");
        else             asm volatile("cp.async.wait_group 0;" ::: "memory");
        __syncthreads();   // chunk c data visible to all

        // ---- MMA: acc = x.w - 0.5||w||^2 via hH + mH + hM ----
        float acc[2][4][4];
        {
            const float* hww = (const float*)(smem + OFF_HWW + buf * 256);
            #pragma unroll
            for (int nt = 0; nt < 4; nt++) {
                float2 hv = *(const float2*)(hww + wn * 32 + nt * 8 + 2 * (lane & 3));
                #pragma unroll
                for (int mt = 0; mt < 2; mt++) {
                    acc[mt][nt][0] = -hv.x; acc[mt][nt][1] = -hv.y;
                    acc[mt][nt][2] = -hv.x; acc[mt][nt][3] = -hv.y;
                }
            }
        }
        #pragma unroll
        for (int kc = 0; kc < 4; kc++) {
            const uint32_t ka = (uint32_t)(kc * 32);
            uint32_t bb[4][2];
            #pragma unroll
            for (int ng = 0; ng < 2; ng++)
                LDSM4(bb[2 * ng][0], bb[2 * ng][1], bb[2 * ng + 1][0], bb[2 * ng + 1][1],
                      bbase + b_off + ka + ng * 16 * ROWB);
            #pragma unroll
            for (int mt = 0; mt < 2; mt++)
                #pragma unroll
                for (int nt = 0; nt < 4; nt++) {
                    MMA(acc[mt][nt], ah[mt][kc], bb[nt]);   // h.H
                    MMA(acc[mt][nt], am[mt][kc], bb[nt]);   // m.H
                }
            #pragma unroll
            for (int ng = 0; ng < 2; ng++)
                LDSM4(bb[2 * ng][0], bb[2 * ng][1], bb[2 * ng + 1][0], bb[2 * ng + 1][1],
                      bbase + 9216 + b_off + ka + ng * 16 * ROWB);
            #pragma unroll
            for (int mt = 0; mt < 2; mt++)
                #pragma unroll
                for (int nt = 0; nt < 4; nt++)
                    MMA(acc[mt][nt], ah[mt][kc], bb[nt]);   // h.M
        }
        __syncthreads();   // buffer fully read; safe to overwrite
        if (c + 2 < NCH) issue_chunk(sb, c + 2, buf, t);

        // ---- scan (registers only; overlaps the in-flight copy) ----
        #pragma unroll
        for (int mt = 0; mt < 2; mt++)
            #pragma unroll
            for (int nt = 0; nt < 4; nt++) {
                const int c0 = c * 64 + wn * 32 + nt * 8 + 2 * (lane & 3);
                #pragma unroll
                for (int rh = 0; rh < 2; rh++) {
                    const int s = mt * 2 + rh;
                    float v0 = acc[mt][nt][rh * 2 + 0];
                    float v1 = acc[mt][nt][rh * 2 + 1];
                    if (v0 > best[s]) { best[s] = v0; bk[s] = c0; }
                    if (v1 > best[s]) { best[s] = v1; bk[s] = c0 + 1; }
                }
            }
    }

    // ---- per-row reduce: width-4 shfl, then combine the 2 n-warps ----
    #pragma unroll
    for (int s = 0; s < 4; s++) {
        float v = best[s]; int bi = bk[s];
        #pragma unroll
        for (int off = 1; off <= 2; off <<= 1) {
            float ov = __shfl_xor_sync(0xffffffffu, v, off);
            int   oi = __shfl_xor_sync(0xffffffffu, bi, off);
            if (ov > v || (ov == v && oi < bi)) { v = ov; bi = oi; }
        }
        if ((lane & 3) == 0) {
            int row = wm * 32 + (s >> 1) * 16 + (s & 1) * 8 + (lane >> 2);
            ((float*)(smem + OFF_SBV))[row * 2 + wn] = v;
            ((int*)(smem + OFF_SBI))[row * 2 + wn] = bi;
        }
    }
    __syncthreads();
    if (t < 128) {
        float v0 = ((float*)(smem + OFF_SBV))[t * 2 + 0];
        float v1 = ((float*)(smem + OFF_SBV))[t * 2 + 1];
        int   i0 = ((int*)(smem + OFF_SBI))[t * 2 + 0];
        int   i1 = ((int*)(smem + OFF_SBI))[t * 2 + 1];
        int k = (v1 > v0 || (v1 == v0 && i1 < i0)) ? i1 : i0;
        ((int*)(smem + OFF_KIDX))[t] = k;
        if (rowbase + t < n_rows) out_idx[rowbase + t] = (float)k;
    }
    __syncthreads();

    // ---- epilogue: q = h+m from pre-split buffers, loss ----
    double lsum = 0.0;
    {
        const int row = t >> 1, hseg = (t & 1) * 32;
        const int grow = rowbase + row;
        if (grow < n_rows) {
            const int k = ((int*)(smem + OFF_KIDX))[row];
            const __half* gh = g_bh + (size_t)k * LDA + hseg;
            const __half* gm = g_bm + (size_t)k * LDA + hseg;
            const __half* ahp = (const __half*)(smem + OFF_AH) + row * LDA + hseg;
            const __half* amp = (const __half*)(smem + OFF_AM) + row * LDA + hseg;
            float4* qo = (float4*)(out_q + (size_t)grow * DD + hseg);
            #pragma unroll
            for (int j = 0; j < 8; j++) {
                float2 wh0 = __half22float2(*(const __half2*)(gh + 4 * j));
                float2 wh1 = __half22float2(*(const __half2*)(gh + 4 * j + 2));
                float2 wm0 = __half22float2(*(const __half2*)(gm + 4 * j));
                float2 wm1 = __half22float2(*(const __half2*)(gm + 4 * j + 2));
                float q0 = wh0.x + wm0.x, q1 = wh0.y + wm0.y;
                float q2 = wh1.x + wm1.x, q3 = wh1.y + wm1.y;
                qo[j] = make_float4(q0, q1, q2, q3);
                float2 a0 = __half22float2(*(const __half2*)(ahp + 4 * j));
                float2 a1 = __half22float2(*(const __half2*)(ahp + 4 * j + 2));
                float2 b0 = __half22float2(*(const __half2*)(amp + 4 * j));
                float2 b1 = __half22float2(*(const __half2*)(amp + 4 * j + 2));
                float e0 = q0 - (a0.x + b0.x);
                float e1 = q1 - (a0.y + b0.y);
                float e2 = q2 - (a1.x + b1.x);
                float e3 = q3 - (a1.y + b1.y);
                lsum += (double)(e0 * e0 + e1 * e1 + e2 * e2 + e3 * e3);
            }
        }
    }

    // ---- loss reduction -> atomic; last block finalizes + resets ----
    #pragma unroll
    for (int off = 16; off; off >>= 1) lsum += __shfl_down_sync(0xffffffffu, lsum, off);
    double* sred = (double*)(smem + OFF_SRED);
    if (lane == 0) sred[w] = lsum;
    __syncthreads();
    if (w == 0) {
        double v = (lane < 8) ? sred[lane] : 0.0;
        v += __shfl_down_sync(0xffffffffu, v, 4);
        v += __shfl_down_sync(0xffffffffu, v, 2);
        v += __shfl_down_sync(0xffffffffu, v, 1);
        if (lane == 0) {
            atomicAdd(&g_loss_sum, v);
            __threadfence();
            unsigned prev = atomicAdd(&g_ctr, 1u);
            if (prev == gridDim.x - 1) {
                __threadfence();
                double total = atomicAdd(&g_loss_sum, 0.0);
                *out_loss = (float)(1.25 * total * inv_count);
                g_loss_sum = 0.0;
                g_ctr = 0u;
            }
        }
    }
}

extern "C" void kernel_launch(void* const* d_in, const int* in_sizes, int n_in,
                              void* d_out, int out_size)
{
    const float* x   = (const float*)d_in[0];   // [N, 64]
    const float* emb = (const float*)d_in[1];   // [64, 512]

    const int n_rows = in_sizes[0] / DD;
    float* out      = (float*)d_out;
    float* out_q    = out;
    float* out_idx  = out + (size_t)n_rows * DD;
    float* out_loss = out_idx + n_rows;

    cudaFuncSetAttribute(vq_main_kernel,
                         cudaFuncAttributeMaxDynamicSharedMemorySize, SMEM_TOTAL);

    int grid = (n_rows + BN - 1) / BN;   // 512

    vq_pre_kernel<<<16, 128>>>(emb);
    vq_main_kernel<<<grid, TPB, SMEM_TOTAL>>>(x, out_q, out_idx, out_loss,
                                              n_rows, 1.0 / ((double)n_rows * (double)DD));
}